// round 3
// baseline (speedup 1.0000x reference)
#include <cuda_runtime.h>

#define BN    16384   // number of segments (power of two)
#define TPB   256     // threads per block
#define WITER 32      // windows (of 32 nodes) per warp -> 1024 nodes/warp

// Scratch (no cudaMalloc allowed). Zero-initialized at module load; the
// epilogue re-zeroes after consuming, so every launch starts from zeros.
__device__ float4 g_sum[BN];
__device__ float  g_cnt[BN];
__device__ unsigned int g_done = 0;

__device__ __forceinline__ void warp_flush(int seg, float4 s, float c, int lane) {
    #pragma unroll
    for (int o = 16; o > 0; o >>= 1) {
        s.x += __shfl_down_sync(0xffffffffu, s.x, o);
        s.y += __shfl_down_sync(0xffffffffu, s.y, o);
        s.z += __shfl_down_sync(0xffffffffu, s.z, o);
        s.w += __shfl_down_sync(0xffffffffu, s.w, o);
        c   += __shfl_down_sync(0xffffffffu, c,   o);
    }
    if (lane == 0) {
        seg &= (BN - 1);
        atomicAdd(&g_sum[seg].x, s.x);
        atomicAdd(&g_sum[seg].y, s.y);
        atomicAdd(&g_sum[seg].z, s.z);
        atomicAdd(&g_sum[seg].w, s.w);
        atomicAdd(&g_cnt[seg],   c);
    }
}

__global__ void __launch_bounds__(TPB) fused_kernel(
    const float4* __restrict__ x,
    const int*    __restrict__ batch,
    int n,
    const float* __restrict__ u,
    const float* __restrict__ W1,  // [5,5] row-major
    const float* __restrict__ b1,  // [5]
    const float* __restrict__ W2,  // [5,1]
    const float* __restrict__ b2,  // [1]
    float* __restrict__ out)
{
    const int lane = threadIdx.x & 31;
    const int warp = blockIdx.x * (TPB / 32) + (threadIdx.x >> 5);
    const long long base = (long long)warp * (32 * WITER);

    // ---------------- phase 1: coalesced segmented reduction ----------------
    if (base < n) {
        int    curseg = 0;
        float4 acc = make_float4(0.f, 0.f, 0.f, 0.f);
        float  cnt = 0.f;

        #pragma unroll 4
        for (int it = 0; it < WITER; ++it) {
            long long idx = base + (long long)it * 32 + lane;
            bool valid = idx < n;
            int    b = valid ? batch[idx] : -1;
            float4 v = valid ? x[idx] : make_float4(0.f, 0.f, 0.f, 0.f);

            if (it == 0) curseg = __shfl_sync(0xffffffffu, b, 0);

            bool match = (b == curseg);
            // fast path: predicated accumulate (no divergent branch)
            if (match) {
                acc.x += v.x; acc.y += v.y; acc.z += v.z; acc.w += v.w;
                cnt   += 1.f;
            }
            if (!__all_sync(0xffffffffu, match || !valid)) {
                // boundary window: flush current segment, start the new one
                warp_flush(curseg, acc, cnt, lane);
                int newseg = __reduce_max_sync(0xffffffffu, b);  // highest valid seg
                acc = make_float4(0.f, 0.f, 0.f, 0.f);
                cnt = 0.f;
                if (valid && b != curseg) {
                    if (b == newseg) {
                        acc = v; cnt = 1.f;
                    } else {
                        // ultra-rare: entire short segment inside this window
                        int s = b & (BN - 1);
                        atomicAdd(&g_sum[s].x, v.x);
                        atomicAdd(&g_sum[s].y, v.y);
                        atomicAdd(&g_sum[s].z, v.z);
                        atomicAdd(&g_sum[s].w, v.w);
                        atomicAdd(&g_cnt[s],   1.f);
                    }
                }
                curseg = newseg;
            }
        }
        warp_flush(curseg, acc, cnt, lane);
    }

    // ---------------- gate: last block runs the epilogue ----------------
    __threadfence();
    __syncthreads();
    __shared__ int s_last;
    if (threadIdx.x == 0) {
        unsigned int old = atomicAdd(&g_done, 1u);
        s_last = (old == gridDim.x - 1) ? 1 : 0;
    }
    __syncthreads();
    if (!s_last) return;

    // ---------------- phase 2: tiny MLP over 16384 segments ----------------
    float w1[25], bb1[5], w2[5];
    #pragma unroll
    for (int k = 0; k < 25; ++k) w1[k] = __ldg(&W1[k]);
    #pragma unroll
    for (int k = 0; k < 5; ++k)  bb1[k] = __ldg(&b1[k]);
    #pragma unroll
    for (int k = 0; k < 5; ++k)  w2[k] = __ldg(&W2[k]);
    float bb2 = __ldg(&b2[0]);

    for (int i = threadIdx.x; i < BN; i += TPB) {
        float  c  = __ldcg(&g_cnt[i]);
        float4 sv = __ldcg(&g_sum[i]);
        float inv = (c > 0.f) ? (1.f / c) : 0.f;

        float h[5];
        h[0] = __ldg(&u[i]);
        h[1] = sv.x * inv; h[2] = sv.y * inv;
        h[3] = sv.z * inv; h[4] = sv.w * inv;

        float o = bb2;
        #pragma unroll
        for (int j = 0; j < 5; ++j) {
            float t = bb1[j];
            #pragma unroll
            for (int k = 0; k < 5; ++k) t += h[k] * w1[k * 5 + j];
            t = (t > 0.f) ? t : 0.1f * t;
            o += t * w2[j];
        }
        out[i] = o;

        // reset scratch for the next graph replay
        g_sum[i] = make_float4(0.f, 0.f, 0.f, 0.f);
        g_cnt[i] = 0.f;
    }
    if (threadIdx.x == 0) g_done = 0;
}

extern "C" void kernel_launch(void* const* d_in, const int* in_sizes, int n_in,
                              void* d_out, int out_size) {
    const float* x     = (const float*)d_in[0];
    const int*   batch = (const int*)d_in[1];
    const float* u     = (const float*)d_in[2];
    const float* W1    = (const float*)d_in[3];
    const float* b1    = (const float*)d_in[4];
    const float* W2    = (const float*)d_in[5];
    const float* b2    = (const float*)d_in[6];
    float* out = (float*)d_out;

    int n = in_sizes[1];  // number of nodes

    long long nwarps  = ((long long)n + (32 * WITER) - 1) / (32 * WITER);
    int       nblocks = (int)((nwarps + (TPB / 32) - 1) / (TPB / 32));
    if (nblocks < 1) nblocks = 1;

    fused_kernel<<<nblocks, TPB>>>((const float4*)x, batch, n,
                                   u, W1, b1, W2, b2, out);
}

// round 4
// speedup vs baseline: 1.8257x; 1.8257x over previous
#include <cuda_runtime.h>

#define BN    16384   // number of segments (power of two)
#define TPB   256     // threads per block
#define ITEMS 32      // strided elements per thread -> 1024 nodes per warp tile
#define U     8       // load-batching chunk

// Scratch (no cudaMalloc). Zero-initialized at module load; mlp_kernel
// re-zeroes after consuming so every launch/replay starts from zeros.
__device__ float4 g_sum[BN];
__device__ float  g_cnt[BN];

__device__ __forceinline__ void flush_seg(int seg, const float4& a, float c) {
    seg &= (BN - 1);
    atomicAdd(&g_sum[seg].x, a.x);
    atomicAdd(&g_sum[seg].y, a.y);
    atomicAdd(&g_sum[seg].z, a.z);
    atomicAdd(&g_sum[seg].w, a.w);
    atomicAdd(&g_cnt[seg],   c);
}

__global__ void __launch_bounds__(TPB) seg_reduce_kernel(
    const float4* __restrict__ x,
    const int*    __restrict__ batch,
    int n)
{
    const int lane = threadIdx.x & 31;
    const long long warp = (long long)blockIdx.x * (TPB / 32) + (threadIdx.x >> 5);
    const long long base = warp * (32 * ITEMS);
    if (base >= n) return;

    float4 acc = make_float4(0.f, 0.f, 0.f, 0.f);
    float  cnt = 0.f;

    if (base + 32 * ITEMS <= n) {
        // ---- fast path: tile fully in range, branch-free loads ----
        int cur = batch[base + lane];   // peek (re-hit in chunk 0 via L1)
        #pragma unroll
        for (int c0 = 0; c0 < ITEMS; c0 += U) {
            int    bs[U];
            float4 vs[U];
            #pragma unroll
            for (int j = 0; j < U; ++j) {
                long long idx = base + (long long)(c0 + j) * 32 + lane;
                bs[j] = batch[idx];
                vs[j] = x[idx];
            }
            #pragma unroll
            for (int j = 0; j < U; ++j) {
                if (bs[j] == cur) {
                    acc.x += vs[j].x; acc.y += vs[j].y;
                    acc.z += vs[j].z; acc.w += vs[j].w;
                    cnt   += 1.f;
                } else {
                    flush_seg(cur, acc, cnt);
                    cur = bs[j];
                    acc = vs[j];
                    cnt = 1.f;
                }
            }
        }
        flush_seg(cur, acc, cnt);
    } else {
        // ---- tail path: per-element bounds checks ----
        int cur = -1;
        for (int it = 0; it < ITEMS; ++it) {
            long long idx = base + (long long)it * 32 + lane;
            if (idx >= n) break;
            int    b = batch[idx];
            float4 v = x[idx];
            if (b == cur) {
                acc.x += v.x; acc.y += v.y; acc.z += v.z; acc.w += v.w;
                cnt   += 1.f;
            } else {
                if (cnt > 0.f) flush_seg(cur, acc, cnt);
                cur = b;
                acc = v;
                cnt = 1.f;
            }
        }
        if (cnt > 0.f) flush_seg(cur, acc, cnt);
    }
}

// Tiny MLP: h = concat(u, mean)[5]; leaky_relu(h@W1+b1, 0.1); @W2+b2 -> out[B,1]
// Also resets the scratch accumulators for the next graph replay.
__global__ void __launch_bounds__(TPB) mlp_kernel(
    const float* __restrict__ u,
    const float* __restrict__ W1,  // [5,5] row-major
    const float* __restrict__ b1,  // [5]
    const float* __restrict__ W2,  // [5,1]
    const float* __restrict__ b2,  // [1]
    float* __restrict__ out)
{
    int i = blockIdx.x * blockDim.x + threadIdx.x;
    if (i >= BN) return;

    float  c  = g_cnt[i];
    float4 sv = g_sum[i];
    float inv = (c > 0.f) ? (1.f / c) : 0.f;

    float h[5];
    h[0] = __ldg(&u[i]);
    h[1] = sv.x * inv; h[2] = sv.y * inv;
    h[3] = sv.z * inv; h[4] = sv.w * inv;

    float o = __ldg(&b2[0]);
    #pragma unroll
    for (int j = 0; j < 5; ++j) {
        float t = __ldg(&b1[j]);
        #pragma unroll
        for (int k = 0; k < 5; ++k) t += h[k] * __ldg(&W1[k * 5 + j]);
        t = (t > 0.f) ? t : 0.1f * t;
        o += t * __ldg(&W2[j]);
    }
    out[i] = o;

    // reset scratch for the next replay
    g_sum[i] = make_float4(0.f, 0.f, 0.f, 0.f);
    g_cnt[i] = 0.f;
}

extern "C" void kernel_launch(void* const* d_in, const int* in_sizes, int n_in,
                              void* d_out, int out_size) {
    const float* x     = (const float*)d_in[0];
    const int*   batch = (const int*)d_in[1];
    const float* u     = (const float*)d_in[2];
    const float* W1    = (const float*)d_in[3];
    const float* b1    = (const float*)d_in[4];
    const float* W2    = (const float*)d_in[5];
    const float* b2    = (const float*)d_in[6];
    float* out = (float*)d_out;

    int n = in_sizes[1];  // number of nodes

    long long nwarps  = ((long long)n + (32 * ITEMS) - 1) / (32 * ITEMS);
    int       nblocks = (int)((nwarps + (TPB / 32) - 1) / (TPB / 32));
    if (nblocks < 1) nblocks = 1;

    seg_reduce_kernel<<<nblocks, TPB>>>((const float4*)x, batch, n);
    mlp_kernel<<<(BN + TPB - 1) / TPB, TPB>>>(u, W1, b1, W2, b2, out);
}